// round 7
// baseline (speedup 1.0000x reference)
#include <cuda_runtime.h>
#include <math.h>

// Problem constants
#define SEQ   256
#define BAT   64
#define EMB   300
#define HID2  256          // H2
#define NJ    2048         // 4*H2 * 2 directions
#define NTAG  10
#define NROWS 16384        // SEQ*BAT
#define NCTA_REC 128       // persistent recurrent CTAs (64 per direction)

typedef unsigned long long ull;

// ---------------- packed fp32x2 helpers (sm_103a FFMA2) ----------------
__device__ __forceinline__ void fma2(ull &d, ull a, ull b) {
    asm("fma.rn.f32x2 %0, %1, %2, %0;" : "+l"(d) : "l"(a), "l"(b));
}
__device__ __forceinline__ float2 unpack2(ull v) {
    float2 r; asm("mov.b64 {%0,%1}, %2;" : "=f"(r.x), "=f"(r.y) : "l"(v)); return r;
}
__device__ __forceinline__ ull pack2(float a, float b) {
    ull v; asm("mov.b64 %0, {%1,%2};" : "=l"(v) : "f"(a), "f"(b)); return v;
}

// ---------------- device scratch (static allocation only) ----------------
__device__ float    g_WT[EMB * NJ];                        // wih transposed, [e][j]
__device__ float    g_P[(size_t)NROWS * NJ];               // input projections + biases
__device__ float    g_hbuf[2 * 2 * BAT * HID2];            // [parity][dir][b][k]
__device__ float    g_Hout[2 * (size_t)NROWS * HID2];      // [dir][s*B+b][k]
__device__ float    g_F[NROWS * NTAG + 64];                // feats (B,S,T) flat, padded
__device__ unsigned g_ctr;                                 // grid barrier counter

// ---------------- kernel 0a: transpose wih into [e][j] ----------------
__global__ void transpose_wih(const float* __restrict__ wf, const float* __restrict__ wb) {
    int idx = blockIdx.x * 256 + threadIdx.x;
    if (idx >= EMB * NJ) return;
    int e = idx / NJ, j = idx % NJ;
    g_WT[idx] = (j < 1024) ? wf[j * EMB + e] : wb[(j - 1024) * EMB + e];
}

// ---------------- kernel 0b: init barrier + copy h0 into hbuf[0] ----------------
__global__ void init_state(const float* __restrict__ h0) {
    int idx = blockIdx.x * 256 + threadIdx.x;
    if (idx == 0) g_ctr = 0u;
    if (idx < 2 * BAT * HID2) g_hbuf[idx] = h0[idx];
}

// ---------------- kernel 1: fused gather + input GEMM (f32x2, 128x64 tile) ----
// P[r][j] = sum_e emb[sent[r]][e] * WT[e][j] + bih[j] + bhh[j]
// M=16384, N=2048, K=300. 128x64 tile, 8x4 per thread, BK=20 (300 = 15*20).
__global__ void __launch_bounds__(256) gemm_input(
    const int* __restrict__ sent, const float* __restrict__ emb,
    const float* __restrict__ bih_f, const float* __restrict__ bhh_f,
    const float* __restrict__ bih_b, const float* __restrict__ bhh_b) {

    __shared__ float As[20][132];    // [k][i], padded stride 132 (16B-aligned rows)
    __shared__ ull   Bs2[20][64];    // [k][j], each value duplicated as (b,b)
    __shared__ int   toks[128];

    int bx = blockIdx.x & 31;        // N tile (32)
    int by = blockIdx.x >> 5;        // M tile (128)
    int tid = threadIdx.x;
    int row0 = by * 128, col0 = bx * 64;

    if (tid < 128) toks[tid] = sent[row0 + tid];
    __syncthreads();

    int ty = tid >> 4, tx = tid & 15;     // 16x16 thread grid; 8 rows x 4 cols each
    int li = tid >> 1;                    // A-load row (2 threads per row)
    int le = (tid & 1) * 10;              // A-load e base (10 elems each)

    ull acc[4][4];                        // [row-pair][col] packed fp32x2
    #pragma unroll
    for (int r = 0; r < 4; r++)
        #pragma unroll
        for (int c = 0; c < 4; c++) acc[r][c] = 0ULL;

    long tokoff = (long)toks[li] * EMB;

    for (int kc = 0; kc < 15; kc++) {
        int e0 = kc * 20;
        // A gather: 128 rows x 20 e-values
        const float* ebase = emb + tokoff + e0 + le;
        #pragma unroll
        for (int q = 0; q < 10; q++) As[le + q][li] = ebase[q];
        // B load (duplicated pairs): 20 x 64 values
        #pragma unroll
        for (int u = 0; u < 5; u++) {
            int idx = tid + u * 256;
            int kk = idx >> 6, j = idx & 63;
            float v = g_WT[(size_t)(e0 + kk) * NJ + col0 + j];
            Bs2[kk][j] = pack2(v, v);
        }
        __syncthreads();
        #pragma unroll
        for (int kk = 0; kk < 20; kk++) {
            ulonglong2 a01 = *(const ulonglong2*)&As[kk][ty * 8];       // rows (0,1),(2,3)
            ulonglong2 a23 = *(const ulonglong2*)&As[kk][ty * 8 + 4];   // rows (4,5),(6,7)
            ulonglong2 b01 = *(const ulonglong2*)&Bs2[kk][tx * 4];      // cols 0,1 dup
            ulonglong2 b23 = *(const ulonglong2*)&Bs2[kk][tx * 4 + 2];  // cols 2,3 dup
            fma2(acc[0][0], a01.x, b01.x); fma2(acc[0][1], a01.x, b01.y);
            fma2(acc[0][2], a01.x, b23.x); fma2(acc[0][3], a01.x, b23.y);
            fma2(acc[1][0], a01.y, b01.x); fma2(acc[1][1], a01.y, b01.y);
            fma2(acc[1][2], a01.y, b23.x); fma2(acc[1][3], a01.y, b23.y);
            fma2(acc[2][0], a23.x, b01.x); fma2(acc[2][1], a23.x, b01.y);
            fma2(acc[2][2], a23.x, b23.x); fma2(acc[2][3], a23.x, b23.y);
            fma2(acc[3][0], a23.y, b01.x); fma2(acc[3][1], a23.y, b01.y);
            fma2(acc[3][2], a23.y, b23.x); fma2(acc[3][3], a23.y, b23.y);
        }
        __syncthreads();
    }

    int jg = col0 + tx * 4;
    float bias[4];
    #pragma unroll
    for (int jj = 0; jj < 4; jj++) {
        int j = jg + jj;
        bias[jj] = (j < 1024) ? (bih_f[j] + bhh_f[j]) : (bih_b[j - 1024] + bhh_b[j - 1024]);
    }
    #pragma unroll
    for (int r = 0; r < 4; r++) {
        float2 c0 = unpack2(acc[r][0]);
        float2 c1 = unpack2(acc[r][1]);
        float2 c2 = unpack2(acc[r][2]);
        float2 c3 = unpack2(acc[r][3]);
        float4 v0 = make_float4(c0.x + bias[0], c1.x + bias[1], c2.x + bias[2], c3.x + bias[3]);
        float4 v1 = make_float4(c0.y + bias[0], c1.y + bias[1], c2.y + bias[2], c3.y + bias[3]);
        int rbase = row0 + ty * 8 + 2 * r;
        *(float4*)&g_P[(size_t)(rbase)     * NJ + jg] = v0;
        *(float4*)&g_P[(size_t)(rbase + 1) * NJ + jg] = v1;
    }
}

// ---------------- kernel 2: persistent bidirectional LSTM recurrence ----------------
// 128 CTAs: dir = bx>>6, each CTA owns 4 hidden units (16 gate rows of Whh in SMEM).
// Per step: prefetch P, broadcast-load h into SMEM, f32x2 gate dot-products,
// gate staging, cell update, write h to double-buffered global + history, grid barrier.
__global__ void __launch_bounds__(256, 1) lstm_recurrent(
    const float* __restrict__ whh_f, const float* __restrict__ whh_b,
    const float* __restrict__ c0) {

    extern __shared__ float sm[];
    float* w_s    = sm;                       // 16 * 268
    float* h_s    = sm + 16 * 268;            // 64 * 256
    float* gate_s = h_s + 64 * 256;           // 16 * 65 (padded)
    float* c_s    = gate_s + 16 * 65;         // 256

    int tid = threadIdx.x;
    int dir = blockIdx.x >> 6;
    int k0  = (blockIdx.x & 63) * 4;
    const float* whh = dir ? whh_b : whh_f;

    // load Whh slice (16 rows x 256) once, float4
    for (int idx = tid; idx < 16 * 64; idx += 256) {
        int jl = idx >> 6, kq = idx & 63;
        int jgl = (jl >> 2) * 256 + k0 + (jl & 3);
        float4 v = *(const float4*)&whh[(size_t)jgl * 256 + kq * 4];
        *(float4*)&w_s[jl * 268 + kq * 4] = v;
    }
    // load cell state slice (persists in SMEM for all 256 steps)
    {
        int b = tid >> 2, kl = tid & 3;
        c_s[tid] = c0[(dir * 64 + b) * 256 + k0 + kl];
    }
    __syncthreads();

    const int jl = tid & 15, bi = tid >> 4;      // dot-product mapping
    const int jg = (jl >> 2) * 256 + k0 + (jl & 3);
    const int bb = tid >> 2, kk2 = tid & 3;      // cell-update mapping

    const ulonglong2* wrow = (const ulonglong2*)(w_s + jl * 268);
    const ulonglong2* h0r  = (const ulonglong2*)(h_s + (bi)      * 256);
    const ulonglong2* h1r  = (const ulonglong2*)(h_s + (bi + 16) * 256);
    const ulonglong2* h2r  = (const ulonglong2*)(h_s + (bi + 32) * 256);
    const ulonglong2* h3r  = (const ulonglong2*)(h_s + (bi + 48) * 256);

    for (int step = 0; step < 256; step++) {
        int p = step & 1;
        int sidx = dir ? (255 - step) : step;

        // prefetch P gate biases (step-independent of h) — hides LDG latency
        const float* Pb = g_P + (size_t)(sidx * 64) * NJ + dir * 1024 + jg;
        float Pv0 = Pb[(size_t)(bi)      * NJ];
        float Pv1 = Pb[(size_t)(bi + 16) * NJ];
        float Pv2 = Pb[(size_t)(bi + 32) * NJ];
        float Pv3 = Pb[(size_t)(bi + 48) * NJ];

        // broadcast-load h (bypass L1: cross-SM producer/consumer)
        {
            const float4* src = (const float4*)(g_hbuf + (p * 2 + dir) * (BAT * HID2));
            float4* dst = (float4*)h_s;
            #pragma unroll
            for (int u = 0; u < 16; u++) dst[tid + u * 256] = __ldcg(src + tid + u * 256);
        }
        __syncthreads();

        // 4 dot products (same gate row, batches bi, bi+16, bi+32, bi+48), f32x2
        ull A00 = 0, A01 = 0, A10 = 0, A11 = 0, A20 = 0, A21 = 0, A30 = 0, A31 = 0;
        #pragma unroll 8
        for (int q = 0; q < 64; q++) {
            ulonglong2 w = wrow[q];
            ulonglong2 x;
            x = h0r[q]; fma2(A00, w.x, x.x); fma2(A01, w.y, x.y);
            x = h1r[q]; fma2(A10, w.x, x.x); fma2(A11, w.y, x.y);
            x = h2r[q]; fma2(A20, w.x, x.x); fma2(A21, w.y, x.y);
            x = h3r[q]; fma2(A30, w.x, x.x); fma2(A31, w.y, x.y);
        }
        {
            float2 u, v;
            u = unpack2(A00); v = unpack2(A01);
            gate_s[jl * 65 + bi]      = (u.x + u.y) + (v.x + v.y) + Pv0;
            u = unpack2(A10); v = unpack2(A11);
            gate_s[jl * 65 + bi + 16] = (u.x + u.y) + (v.x + v.y) + Pv1;
            u = unpack2(A20); v = unpack2(A21);
            gate_s[jl * 65 + bi + 32] = (u.x + u.y) + (v.x + v.y) + Pv2;
            u = unpack2(A30); v = unpack2(A31);
            gate_s[jl * 65 + bi + 48] = (u.x + u.y) + (v.x + v.y) + Pv3;
        }
        __syncthreads();

        // cell/hidden update: gate order i,f,g,o
        {
            float gi = gate_s[(0  + kk2) * 65 + bb];
            float gf = gate_s[(4  + kk2) * 65 + bb];
            float gg = gate_s[(8  + kk2) * 65 + bb];
            float go = gate_s[(12 + kk2) * 65 + bb];
            float si = 1.f / (1.f + expf(-gi));
            float sf = 1.f / (1.f + expf(-gf));
            float so = 1.f / (1.f + expf(-go));
            float c = sf * c_s[tid] + si * tanhf(gg);
            c_s[tid] = c;
            float h = so * tanhf(c);
            __stcg(&g_hbuf[((p ^ 1) * 2 + dir) * (BAT * HID2) + bb * 256 + k0 + kk2], h);
            g_Hout[(size_t)dir * ((size_t)NROWS * HID2) + (size_t)(sidx * 64 + bb) * 256 + k0 + kk2] = h;
        }

        // grid-wide barrier (all 128 CTAs co-resident: 128 <= 148 SMs, 1 CTA/SM)
        __threadfence();
        __syncthreads();
        if (tid == 0) {
            atomicAdd(&g_ctr, 1u);
            unsigned target = (unsigned)NCTA_REC * (unsigned)(step + 1);
            while (*((volatile unsigned*)&g_ctr) < target) { }
        }
        __syncthreads();
    }
}

// ---------------- kernel 3: output features F[r][t] ----------------
__global__ void __launch_bounds__(256) feats_kernel(
    const float* __restrict__ Wout, const float* __restrict__ bout) {
    int warp = threadIdx.x >> 5;
    int lane = threadIdx.x & 31;
    int r = blockIdx.x * 8 + warp;
    const float* hf = g_Hout + (size_t)r * 256;
    const float* hb = g_Hout + (size_t)NROWS * HID2 + (size_t)r * 256;
    float a[8], c[8];
    #pragma unroll
    for (int q = 0; q < 8; q++) { a[q] = hf[lane * 8 + q]; c[q] = hb[lane * 8 + q]; }
    #pragma unroll
    for (int t = 0; t < NTAG; t++) {
        const float* w = Wout + t * 512 + lane * 8;
        float s = 0.f;
        #pragma unroll
        for (int q = 0; q < 8; q++) s += a[q] * w[q] + c[q] * w[256 + q];
        #pragma unroll
        for (int off = 16; off; off >>= 1) s += __shfl_xor_sync(0xffffffffu, s, off);
        if (lane == 0) g_F[r * NTAG + t] = s + bout[t];
    }
}

// ---------------- kernel 4: Viterbi decode (one warp per batch) ----------------
__global__ void viterbi_kernel(const float* __restrict__ trans, float* __restrict__ out) {
    int b = blockIdx.x;
    int lane = threadIdx.x;
    __shared__ unsigned char bps[256][16];

    float tr[NTAG];
    if (lane < NTAG) {
        #pragma unroll
        for (int p = 0; p < NTAG; p++) tr[p] = trans[lane * NTAG + p];
    } else {
        #pragma unroll
        for (int p = 0; p < NTAG; p++) tr[p] = -10000.0f;
    }
    float fv = (lane == 8) ? 0.f : -10000.0f;   // START_IDX = 8
    const float* fb = g_F + b * (SEQ * NTAG);

    for (int s = 0; s < SEQ; s++) {
        float m = -3.4e38f; int arg = 0;
        #pragma unroll
        for (int p = 0; p < NTAG; p++) {
            float v = __shfl_sync(0xffffffffu, fv, p) + tr[p];
            if (v > m) { m = v; arg = p; }      // strict >: first-max wins (jnp.argmax)
        }
        float feat = 0.f;
        if (lane < NTAG) feat = fb[s * NTAG + lane];
        fv = m + feat;
        if (lane < NTAG) bps[s][lane] = (unsigned char)arg;
    }

    float term = fv;
    if (lane < NTAG) term += trans[9 * NTAG + lane];   // STOP_IDX row = 9
    float best = -3.4e38f; int bt = 0;
    #pragma unroll
    for (int t = 0; t < NTAG; t++) {
        float v = __shfl_sync(0xffffffffu, term, t);
        if (v > best) { best = v; bt = t; }
    }
    __syncwarp();
    if (lane == 0) {
        out[b] = best;                                   // path_score (B,1)
        int cur = bt;
        out[64 + b * SEQ + (SEQ - 1)] = (float)cur;      // path (B,S)
        for (int s = SEQ - 2; s >= 0; s--) {
            cur = bps[s + 1][cur];
            out[64 + b * SEQ + s] = (float)cur;
        }
    }
}

// ---------------- launch ----------------
extern "C" void kernel_launch(void* const* d_in, const int* in_sizes, int n_in,
                              void* d_out, int out_size) {
    const int*   sent  = (const int*)d_in[0];
    const float* emb   = (const float*)d_in[1];
    const float* wih_f = (const float*)d_in[2];
    const float* whh_f = (const float*)d_in[3];
    const float* bih_f = (const float*)d_in[4];
    const float* bhh_f = (const float*)d_in[5];
    const float* wih_b = (const float*)d_in[6];
    const float* whh_b = (const float*)d_in[7];
    const float* bih_b = (const float*)d_in[8];
    const float* bhh_b = (const float*)d_in[9];
    const float* Wout  = (const float*)d_in[10];
    const float* bout  = (const float*)d_in[11];

    // Dict order has transitions last; signature order has it at index 12.
    const float *trans, *h0, *c0;
    if (n_in > 14 && in_sizes[12] == 100) {
        trans = (const float*)d_in[12]; h0 = (const float*)d_in[13]; c0 = (const float*)d_in[14];
    } else {
        h0 = (const float*)d_in[12]; c0 = (const float*)d_in[13]; trans = (const float*)d_in[14];
    }
    float* out = (float*)d_out;

    transpose_wih<<<(EMB * NJ + 255) / 256, 256>>>(wih_f, wih_b);
    init_state<<<128, 256>>>(h0);
    gemm_input<<<4096, 256>>>(sent, emb, bih_f, bhh_f, bih_b, bhh_b);

    const int smem_rec = (16 * 268 + 64 * 256 + 16 * 65 + 256) * (int)sizeof(float); // 87872 B
    cudaFuncSetAttribute(lstm_recurrent, cudaFuncAttributeMaxDynamicSharedMemorySize, smem_rec);
    lstm_recurrent<<<NCTA_REC, 256, smem_rec>>>(whh_f, whh_b, c0);

    feats_kernel<<<NROWS / 8, 256>>>(Wout, bout);
    viterbi_kernel<<<BAT, 32>>>(trans, out);
}

// round 8
// speedup vs baseline: 1.0930x; 1.0930x over previous
#include <cuda_runtime.h>
#include <math.h>

// Problem constants
#define SEQ   256
#define BAT   64
#define EMB   300
#define HID2  256          // H2
#define NJ    2048         // 4*H2 * 2 directions
#define NTAG  10
#define NROWS 16384        // SEQ*BAT
#define NCTA_REC 128       // persistent recurrent CTAs (64 per direction)

typedef unsigned long long ull;

// ---------------- packed fp32x2 helpers (sm_103a FFMA2) ----------------
__device__ __forceinline__ void fma2(ull &d, ull a, ull b) {
    asm("fma.rn.f32x2 %0, %1, %2, %0;" : "+l"(d) : "l"(a), "l"(b));
}
__device__ __forceinline__ float2 unpack2(ull v) {
    float2 r; asm("mov.b64 {%0,%1}, %2;" : "=f"(r.x), "=f"(r.y) : "l"(v)); return r;
}

// ---------------- device scratch (static allocation only) ----------------
__device__ float    g_WT[EMB * NJ];                        // wih transposed, [e][j]
__device__ float    g_P[(size_t)NROWS * NJ];               // input projections + biases
// h exchange, chunk-major: [slot(2)][dir(2)][chunk g(64)][b(64)][kk(4)]
__device__ float    g_hbuf[2 * 2 * 64 * BAT * 4];
__device__ float    g_Hout[2 * (size_t)NROWS * HID2];      // [dir][s*B+b][k]
__device__ float    g_F[NROWS * NTAG + 64];                // feats (B,S,T) flat, padded
// per-producer flags, one 128B line each: g_flags[dir][g*32]
__device__ unsigned g_flags[2 * 64 * 32];

// ---------------- kernel 0a: transpose wih into [e][j] ----------------
__global__ void transpose_wih(const float* __restrict__ wf, const float* __restrict__ wb) {
    int idx = blockIdx.x * 256 + threadIdx.x;
    if (idx >= EMB * NJ) return;
    int e = idx / NJ, j = idx % NJ;
    g_WT[idx] = (j < 1024) ? wf[j * EMB + e] : wb[(j - 1024) * EMB + e];
}

// ---------------- kernel 0b: zero flags + copy h0 into slot 0 (chunk layout) ----
__global__ void init_state(const float* __restrict__ h0) {
    int idx = blockIdx.x * 256 + threadIdx.x;
    if (idx < 2 * 64 * 32) g_flags[idx] = 0u;
    if (idx < 2 * BAT * HID2) {
        // h0 is [dir][b][k]
        int dir = idx >> 14;
        int b = (idx >> 8) & 63;
        int k = idx & 255;
        int g = k >> 2, kk = k & 3;
        g_hbuf[((0 * 2 + dir) * 64 + g) * 256 + b * 4 + kk] = h0[idx];
    }
}

// ---------------- kernel 1: fused gather + input GEMM (fp32, 64x64 tile) ----
// P[r][j] = sum_e emb[sent[r]][e] * WT[e][j] + bih[j] + bhh[j]
__global__ void __launch_bounds__(256) gemm_input(
    const int* __restrict__ sent, const float* __restrict__ emb,
    const float* __restrict__ bih_f, const float* __restrict__ bhh_f,
    const float* __restrict__ bih_b, const float* __restrict__ bhh_b) {

    __shared__ float As[20][68];   // [k][i], padded stride 68
    __shared__ float Bs[20][64];   // [k][j]
    __shared__ int   toks[64];

    int bx = blockIdx.x & 31;      // N tile (32)
    int by = blockIdx.x >> 5;      // M tile (256)
    int tid = threadIdx.x;
    int row0 = by * 64, col0 = bx * 64;

    if (tid < 64) toks[tid] = sent[row0 + tid];
    __syncthreads();

    int ty = tid >> 4, tx = tid & 15;         // 16x16 thread grid
    int li = tid >> 2;                        // A-load row
    int le = (tid & 3) * 5;                   // A-load e base

    float4 acc[4];
    #pragma unroll
    for (int i = 0; i < 4; i++) acc[i] = make_float4(0.f, 0.f, 0.f, 0.f);

    long tokoff = (long)toks[li] * EMB;

    for (int kc = 0; kc < 15; kc++) {
        int e0 = kc * 20;
        const float* ebase = emb + tokoff + e0 + le;
        #pragma unroll
        for (int q = 0; q < 5; q++) As[le + q][li] = ebase[q];
        #pragma unroll
        for (int u = 0; u < 5; u++) {
            int idx = tid + u * 256;
            int kk = idx >> 6, j = idx & 63;
            Bs[kk][j] = g_WT[(size_t)(e0 + kk) * NJ + col0 + j];
        }
        __syncthreads();
        #pragma unroll
        for (int kk = 0; kk < 20; kk++) {
            float4 b4 = *(const float4*)&Bs[kk][tx * 4];
            float4 a4 = *(const float4*)&As[kk][ty * 4];
            acc[0].x += a4.x * b4.x; acc[0].y += a4.x * b4.y; acc[0].z += a4.x * b4.z; acc[0].w += a4.x * b4.w;
            acc[1].x += a4.y * b4.x; acc[1].y += a4.y * b4.y; acc[1].z += a4.y * b4.z; acc[1].w += a4.y * b4.w;
            acc[2].x += a4.z * b4.x; acc[2].y += a4.z * b4.y; acc[2].z += a4.z * b4.z; acc[2].w += a4.z * b4.w;
            acc[3].x += a4.w * b4.x; acc[3].y += a4.w * b4.y; acc[3].z += a4.w * b4.z; acc[3].w += a4.w * b4.w;
        }
        __syncthreads();
    }

    int jg = col0 + tx * 4;
    float bias[4];
    #pragma unroll
    for (int jj = 0; jj < 4; jj++) {
        int j = jg + jj;
        bias[jj] = (j < 1024) ? (bih_f[j] + bhh_f[j]) : (bih_b[j - 1024] + bhh_b[j - 1024]);
    }
    #pragma unroll
    for (int ii = 0; ii < 4; ii++) {
        float4 v = acc[ii];
        v.x += bias[0]; v.y += bias[1]; v.z += bias[2]; v.w += bias[3];
        *(float4*)&g_P[(size_t)(row0 + ty * 4 + ii) * NJ + jg] = v;
    }
}

// ---------------- kernel 2: persistent bidirectional LSTM recurrence ----------------
// 128 CTAs: dir = bx>>6, each CTA owns 4 hidden units (16 gate rows of Whh in SMEM).
// h exchange via chunk-major double buffer + per-producer release flags.
// No central atomic counter: consumers pipeline chunk loads on per-chunk flags.
__global__ void __launch_bounds__(256, 1) lstm_recurrent(
    const float* __restrict__ whh_f, const float* __restrict__ whh_b,
    const float* __restrict__ c0) {

    extern __shared__ float sm[];
    float* w_s    = sm;                       // 16 * 268
    float* h_s    = sm + 16 * 268;            // 64 chunks * 256 floats (chunk-major)
    float* gate_s = h_s + 64 * 256;           // 16 * 65 (padded)
    float* c_s    = gate_s + 16 * 65;         // 256

    int tid = threadIdx.x;
    int dir = blockIdx.x >> 6;
    int gown = blockIdx.x & 63;               // chunk this CTA produces
    int k0  = gown * 4;
    const float* whh = dir ? whh_b : whh_f;

    // load Whh slice (16 rows x 256) once, float4
    for (int idx = tid; idx < 16 * 64; idx += 256) {
        int jl = idx >> 6, kq = idx & 63;
        int jgl = (jl >> 2) * 256 + k0 + (jl & 3);
        float4 v = *(const float4*)&whh[(size_t)jgl * 256 + kq * 4];
        *(float4*)&w_s[jl * 268 + kq * 4] = v;
    }
    // cell state slice (persists in SMEM for all 256 steps)
    {
        int b = tid >> 2, kl = tid & 3;
        c_s[tid] = c0[(dir * 64 + b) * 256 + k0 + kl];
    }
    __syncthreads();

    const int jl = tid & 15, bi = tid >> 4;      // dot-product mapping
    const int jg = (jl >> 2) * 256 + k0 + (jl & 3);
    const int bb = tid >> 2, kk2 = tid & 3;      // cell-update / producer mapping

    // consumer chunk-copy mapping: 4 threads per chunk
    const int cg = tid >> 2;                     // chunk to fetch
    const int cq = tid & 3;                      // lane within fetch group
    unsigned* myflag = &g_flags[(dir * 64 + cg) * 32];
    unsigned* ownflag = &g_flags[(dir * 64 + gown) * 32];

    const ull* wrow = (const ull*)(w_s + jl * 268);

    for (int step = 0; step < 256; step++) {
        int slot = step & 1;
        int sidx = dir ? (255 - step) : step;

        // prefetch P gate biases (step-independent of h)
        const float* Pb = g_P + (size_t)(sidx * 64) * NJ + dir * 1024 + jg;
        float Pv0 = Pb[(size_t)(bi)      * NJ];
        float Pv1 = Pb[(size_t)(bi + 16) * NJ];
        float Pv2 = Pb[(size_t)(bi + 32) * NJ];
        float Pv3 = Pb[(size_t)(bi + 48) * NJ];

        // wait for chunk cg of h(step), then copy its 1KB into SMEM.
        // flag value f means h(f) is published (h(0)=h0 published at init, flag 0).
        {
            unsigned v;
            do {
                asm volatile("ld.acquire.gpu.b32 %0, [%1];" : "=r"(v) : "l"(myflag) : "memory");
            } while ((int)v < step);
            const float4* src = (const float4*)(g_hbuf + ((slot * 2 + dir) * 64 + cg) * 256);
            float4* dst = (float4*)(h_s + cg * 256);
            #pragma unroll
            for (int i = 0; i < 16; i++) dst[cq + 4 * i] = __ldcg(src + cq + 4 * i);
        }
        __syncthreads();

        // 4 dot products (gate row jl*, batches bi, bi+16, bi+32, bi+48), f32x2
        // h_s chunk-major: chunk g holds k=4g..4g+3 for all b at [g*256 + b*4]
        ull A00 = 0, A01 = 0, A10 = 0, A11 = 0, A20 = 0, A21 = 0, A30 = 0, A31 = 0;
        const ull* h0r = (const ull*)(h_s + bi * 4);
        const ull* h1r = (const ull*)(h_s + (bi + 16) * 4);
        const ull* h2r = (const ull*)(h_s + (bi + 32) * 4);
        const ull* h3r = (const ull*)(h_s + (bi + 48) * 4);
        #pragma unroll 8
        for (int g = 0; g < 64; g++) {
            ull w0 = wrow[2 * g], w1 = wrow[2 * g + 1];
            ull x0, x1;
            x0 = h0r[g * 128];     x1 = h0r[g * 128 + 1];
            fma2(A00, w0, x0); fma2(A01, w1, x1);
            x0 = h1r[g * 128];     x1 = h1r[g * 128 + 1];
            fma2(A10, w0, x0); fma2(A11, w1, x1);
            x0 = h2r[g * 128];     x1 = h2r[g * 128 + 1];
            fma2(A20, w0, x0); fma2(A21, w1, x1);
            x0 = h3r[g * 128];     x1 = h3r[g * 128 + 1];
            fma2(A30, w0, x0); fma2(A31, w1, x1);
        }
        {
            float2 u, v;
            u = unpack2(A00); v = unpack2(A01);
            gate_s[jl * 65 + bi]      = (u.x + u.y) + (v.x + v.y) + Pv0;
            u = unpack2(A10); v = unpack2(A11);
            gate_s[jl * 65 + bi + 16] = (u.x + u.y) + (v.x + v.y) + Pv1;
            u = unpack2(A20); v = unpack2(A21);
            gate_s[jl * 65 + bi + 32] = (u.x + u.y) + (v.x + v.y) + Pv2;
            u = unpack2(A30); v = unpack2(A31);
            gate_s[jl * 65 + bi + 48] = (u.x + u.y) + (v.x + v.y) + Pv3;
        }
        __syncthreads();

        // cell/hidden update: gate order i,f,g,o
        {
            float gi = gate_s[(0  + kk2) * 65 + bb];
            float gf = gate_s[(4  + kk2) * 65 + bb];
            float gg = gate_s[(8  + kk2) * 65 + bb];
            float go = gate_s[(12 + kk2) * 65 + bb];
            float si = 1.f / (1.f + expf(-gi));
            float sf = 1.f / (1.f + expf(-gf));
            float so = 1.f / (1.f + expf(-go));
            float c = sf * c_s[tid] + si * tanhf(gg);
            c_s[tid] = c;
            float h = so * tanhf(c);
            // publish h(step+1) into slot (step+1)&1, chunk gown (contiguous 1KB)
            __stcg(&g_hbuf[(((slot ^ 1) * 2 + dir) * 64 + gown) * 256 + bb * 4 + kk2], h);
            g_Hout[(size_t)dir * ((size_t)NROWS * HID2) + (size_t)(sidx * 64 + bb) * 256 + k0 + kk2] = h;
        }

        // publish flag = step+1 (release; syncthreads orders all threads' stores)
        __syncthreads();
        __threadfence();
        if (tid == 0) {
            unsigned nv = (unsigned)(step + 1);
            asm volatile("st.release.gpu.b32 [%0], %1;" :: "l"(ownflag), "r"(nv) : "memory");
        }
        // NOTE: no second barrier needed — consumers gate on flags per chunk.
    }
}

// ---------------- kernel 3: output features F[r][t] ----------------
__global__ void __launch_bounds__(256) feats_kernel(
    const float* __restrict__ Wout, const float* __restrict__ bout) {
    int warp = threadIdx.x >> 5;
    int lane = threadIdx.x & 31;
    int r = blockIdx.x * 8 + warp;
    const float* hf = g_Hout + (size_t)r * 256;
    const float* hb = g_Hout + (size_t)NROWS * HID2 + (size_t)r * 256;
    float a[8], c[8];
    #pragma unroll
    for (int q = 0; q < 8; q++) { a[q] = hf[lane * 8 + q]; c[q] = hb[lane * 8 + q]; }
    #pragma unroll
    for (int t = 0; t < NTAG; t++) {
        const float* w = Wout + t * 512 + lane * 8;
        float s = 0.f;
        #pragma unroll
        for (int q = 0; q < 8; q++) s += a[q] * w[q] + c[q] * w[256 + q];
        #pragma unroll
        for (int off = 16; off; off >>= 1) s += __shfl_xor_sync(0xffffffffu, s, off);
        if (lane == 0) g_F[r * NTAG + t] = s + bout[t];
    }
}

// ---------------- kernel 4: Viterbi decode (one warp per batch) ----------------
__global__ void viterbi_kernel(const float* __restrict__ trans, float* __restrict__ out) {
    int b = blockIdx.x;
    int lane = threadIdx.x;
    __shared__ unsigned char bps[256][16];

    float tr[NTAG];
    if (lane < NTAG) {
        #pragma unroll
        for (int p = 0; p < NTAG; p++) tr[p] = trans[lane * NTAG + p];
    } else {
        #pragma unroll
        for (int p = 0; p < NTAG; p++) tr[p] = -10000.0f;
    }
    float fv = (lane == 8) ? 0.f : -10000.0f;   // START_IDX = 8
    const float* fb = g_F + b * (SEQ * NTAG);

    for (int s = 0; s < SEQ; s++) {
        float m = -3.4e38f; int arg = 0;
        #pragma unroll
        for (int p = 0; p < NTAG; p++) {
            float v = __shfl_sync(0xffffffffu, fv, p) + tr[p];
            if (v > m) { m = v; arg = p; }      // strict >: first-max wins (jnp.argmax)
        }
        float feat = 0.f;
        if (lane < NTAG) feat = fb[s * NTAG + lane];
        fv = m + feat;
        if (lane < NTAG) bps[s][lane] = (unsigned char)arg;
    }

    float term = fv;
    if (lane < NTAG) term += trans[9 * NTAG + lane];   // STOP_IDX row = 9
    float best = -3.4e38f; int bt = 0;
    #pragma unroll
    for (int t = 0; t < NTAG; t++) {
        float v = __shfl_sync(0xffffffffu, term, t);
        if (v > best) { best = v; bt = t; }
    }
    __syncwarp();
    if (lane == 0) {
        out[b] = best;                                   // path_score (B,1)
        int cur = bt;
        out[64 + b * SEQ + (SEQ - 1)] = (float)cur;      // path (B,S)
        for (int s = SEQ - 2; s >= 0; s--) {
            cur = bps[s + 1][cur];
            out[64 + b * SEQ + s] = (float)cur;
        }
    }
}

// ---------------- launch ----------------
extern "C" void kernel_launch(void* const* d_in, const int* in_sizes, int n_in,
                              void* d_out, int out_size) {
    const int*   sent  = (const int*)d_in[0];
    const float* emb   = (const float*)d_in[1];
    const float* wih_f = (const float*)d_in[2];
    const float* whh_f = (const float*)d_in[3];
    const float* bih_f = (const float*)d_in[4];
    const float* bhh_f = (const float*)d_in[5];
    const float* wih_b = (const float*)d_in[6];
    const float* whh_b = (const float*)d_in[7];
    const float* bih_b = (const float*)d_in[8];
    const float* bhh_b = (const float*)d_in[9];
    const float* Wout  = (const float*)d_in[10];
    const float* bout  = (const float*)d_in[11];

    // Dict order has transitions last; signature order has it at index 12.
    const float *trans, *h0, *c0;
    if (n_in > 14 && in_sizes[12] == 100) {
        trans = (const float*)d_in[12]; h0 = (const float*)d_in[13]; c0 = (const float*)d_in[14];
    } else {
        h0 = (const float*)d_in[12]; c0 = (const float*)d_in[13]; trans = (const float*)d_in[14];
    }
    float* out = (float*)d_out;

    transpose_wih<<<(EMB * NJ + 255) / 256, 256>>>(wih_f, wih_b);
    init_state<<<128, 256>>>(h0);
    gemm_input<<<8192, 256>>>(sent, emb, bih_f, bhh_f, bih_b, bhh_b);

    const int smem_rec = (16 * 268 + 64 * 256 + 16 * 65 + 256) * (int)sizeof(float); // 87872 B
    cudaFuncSetAttribute(lstm_recurrent, cudaFuncAttributeMaxDynamicSharedMemorySize, smem_rec);
    lstm_recurrent<<<NCTA_REC, 256, smem_rec>>>(whh_f, whh_b, c0);

    feats_kernel<<<NROWS / 8, 256>>>(Wout, bout);
    viterbi_kernel<<<BAT, 32>>>(trans, out);
}

// round 11
// speedup vs baseline: 1.1493x; 1.0515x over previous
#include <cuda_runtime.h>
#include <math.h>

// Problem constants
#define SEQ   256
#define BAT   64
#define EMB   300
#define HID2  256          // H2
#define NJ    2048         // 4*H2 * 2 directions
#define NTAG  10
#define NROWS 16384        // SEQ*BAT
#define NCTA_REC 128       // persistent recurrent CTAs (64 per direction)

typedef unsigned long long ull;

// ---------------- packed fp32x2 helpers (sm_103a FFMA2) ----------------
__device__ __forceinline__ void fma2(ull &d, ull a, ull b) {
    asm("fma.rn.f32x2 %0, %1, %2, %0;" : "+l"(d) : "l"(a), "l"(b));
}
__device__ __forceinline__ float2 unpack2(ull v) {
    float2 r; asm("mov.b64 {%0,%1}, %2;" : "=f"(r.x), "=f"(r.y) : "l"(v)); return r;
}

// ---------------- device scratch (static allocation only) ----------------
__device__ float    g_WT[EMB * NJ];                        // wih transposed, [e][j]
__device__ float    g_P[(size_t)NROWS * NJ];               // input projections + biases
// h exchange, chunk-major: [slot(2)][dir(2)][chunk g(64)][b(64)][kk(4)]
__device__ float    g_hbuf[2 * 2 * 64 * BAT * 4];
__device__ float    g_Hout[2 * (size_t)NROWS * HID2];      // [dir][s*B+b][k]
__device__ float    g_F[NROWS * NTAG + 64];                // feats (B,S,T) flat, padded
// per-producer flags, one 128B line each: g_flags[dir][g*32]
__device__ unsigned g_flags[2 * 64 * 32];

// ---------------- kernel 0a: transpose wih into [e][j] ----------------
__global__ void transpose_wih(const float* __restrict__ wf, const float* __restrict__ wb) {
    int idx = blockIdx.x * 256 + threadIdx.x;
    if (idx >= EMB * NJ) return;
    int e = idx / NJ, j = idx % NJ;
    g_WT[idx] = (j < 1024) ? wf[j * EMB + e] : wb[(j - 1024) * EMB + e];
}

// ---------------- kernel 0b: zero flags + copy h0 into slot 0 (chunk layout) ----
__global__ void init_state(const float* __restrict__ h0) {
    int idx = blockIdx.x * 256 + threadIdx.x;
    if (idx < 2 * 64 * 32) g_flags[idx] = 0u;
    if (idx < 2 * BAT * HID2) {
        // h0 is [dir][b][k]
        int dir = idx >> 14;
        int b = (idx >> 8) & 63;
        int k = idx & 255;
        int g = k >> 2, kk = k & 3;
        g_hbuf[((0 * 2 + dir) * 64 + g) * 256 + b * 4 + kk] = h0[idx];
    }
}

// ---------------- kernel 1: fused gather + input GEMM (fp32, 64x64 tile) ----
// P[r][j] = sum_e emb[sent[r]][e] * WT[e][j] + bih[j] + bhh[j]
__global__ void __launch_bounds__(256) gemm_input(
    const int* __restrict__ sent, const float* __restrict__ emb,
    const float* __restrict__ bih_f, const float* __restrict__ bhh_f,
    const float* __restrict__ bih_b, const float* __restrict__ bhh_b) {

    __shared__ float As[20][68];   // [k][i], padded stride 68
    __shared__ float Bs[20][64];   // [k][j]
    __shared__ int   toks[64];

    int bx = blockIdx.x & 31;      // N tile (32)
    int by = blockIdx.x >> 5;      // M tile (256)
    int tid = threadIdx.x;
    int row0 = by * 64, col0 = bx * 64;

    if (tid < 64) toks[tid] = sent[row0 + tid];
    __syncthreads();

    int ty = tid >> 4, tx = tid & 15;         // 16x16 thread grid
    int li = tid >> 2;                        // A-load row
    int le = (tid & 3) * 5;                   // A-load e base

    float4 acc[4];
    #pragma unroll
    for (int i = 0; i < 4; i++) acc[i] = make_float4(0.f, 0.f, 0.f, 0.f);

    long tokoff = (long)toks[li] * EMB;

    for (int kc = 0; kc < 15; kc++) {
        int e0 = kc * 20;
        const float* ebase = emb + tokoff + e0 + le;
        #pragma unroll
        for (int q = 0; q < 5; q++) As[le + q][li] = ebase[q];
        #pragma unroll
        for (int u = 0; u < 5; u++) {
            int idx = tid + u * 256;
            int kk = idx >> 6, j = idx & 63;
            Bs[kk][j] = g_WT[(size_t)(e0 + kk) * NJ + col0 + j];
        }
        __syncthreads();
        #pragma unroll
        for (int kk = 0; kk < 20; kk++) {
            float4 b4 = *(const float4*)&Bs[kk][tx * 4];
            float4 a4 = *(const float4*)&As[kk][ty * 4];
            acc[0].x += a4.x * b4.x; acc[0].y += a4.x * b4.y; acc[0].z += a4.x * b4.z; acc[0].w += a4.x * b4.w;
            acc[1].x += a4.y * b4.x; acc[1].y += a4.y * b4.y; acc[1].z += a4.y * b4.z; acc[1].w += a4.y * b4.w;
            acc[2].x += a4.z * b4.x; acc[2].y += a4.z * b4.y; acc[2].z += a4.z * b4.z; acc[2].w += a4.z * b4.w;
            acc[3].x += a4.w * b4.x; acc[3].y += a4.w * b4.y; acc[3].z += a4.w * b4.z; acc[3].w += a4.w * b4.w;
        }
        __syncthreads();
    }

    int jg = col0 + tx * 4;
    float bias[4];
    #pragma unroll
    for (int jj = 0; jj < 4; jj++) {
        int j = jg + jj;
        bias[jj] = (j < 1024) ? (bih_f[j] + bhh_f[j]) : (bih_b[j - 1024] + bhh_b[j - 1024]);
    }
    #pragma unroll
    for (int ii = 0; ii < 4; ii++) {
        float4 v = acc[ii];
        v.x += bias[0]; v.y += bias[1]; v.z += bias[2]; v.w += bias[3];
        *(float4*)&g_P[(size_t)(row0 + ty * 4 + ii) * NJ + jg] = v;
    }
}

// ---------------- kernel 2: persistent bidirectional LSTM recurrence ----------------
// 128 CTAs: dir = bx>>6, each CTA owns 4 hidden units (16 gate rows of Whh in SMEM).
// Compute mapping (LDS-traffic-minimizing):
//   warp w handles ALL 16 gate rows x batches [8w, 8w+8), k split in 2 halves.
//   lane = (row 0-15, khalf); h reads are warp-broadcast (cheap), w reads lane-distinct.
//   k-half partials combined via one shfl_xor(16) per accumulator.
// h exchange via chunk-major double buffer + per-producer release flags (as R8).
__global__ void __launch_bounds__(256, 1) lstm_recurrent(
    const float* __restrict__ whh_f, const float* __restrict__ whh_b,
    const float* __restrict__ c0) {

    extern __shared__ float sm[];
    float* w_s    = sm;                       // 16 rows * stride 260       = 4160
    float* h_s    = sm + 4160;                // 64 batches * stride 260    = 16640
    float* gate_s = h_s + 16640;              // 16 rows * stride 72        = 1152
    float* c_s    = gate_s + 1152;            // 256
    // total 22208 floats = 88832 B

    int tid = threadIdx.x;
    int dir = blockIdx.x >> 6;
    int gown = blockIdx.x & 63;               // chunk this CTA produces
    int k0  = gown * 4;
    const float* whh = dir ? whh_b : whh_f;

    // load Whh slice (16 rows x 256, row-major, stride 260) once
    for (int idx = tid; idx < 16 * 64; idx += 256) {
        int r = idx >> 6, kq = idx & 63;
        int grow = (r >> 2) * 256 + k0 + (r & 3);
        float4 v = *(const float4*)&whh[(size_t)grow * 256 + kq * 4];
        *(float4*)&w_s[r * 260 + kq * 4] = v;
    }
    // cell state slice (persists in SMEM for all 256 steps)
    {
        int b = tid >> 2, kl = tid & 3;
        c_s[tid] = c0[(dir * 64 + b) * 256 + k0 + kl];
    }
    __syncthreads();

    const int lane = tid & 31, wrp = tid >> 5;
    const int row  = lane & 15, khalf = lane >> 4;   // compute mapping
    const int b0   = wrp * 8;
    const int growp = (row >> 2) * 256 + k0 + (row & 3);  // global W row for P offset

    const int bb = tid >> 2, kk2 = tid & 3;          // cell-update / producer mapping

    // consumer chunk-copy mapping: 4 threads per chunk
    const int cg = tid >> 2;                         // chunk to fetch
    const int cq = tid & 3;
    unsigned* myflag  = &g_flags[(dir * 64 + cg) * 32];
    unsigned* ownflag = &g_flags[(dir * 64 + gown) * 32];

    // k-half base pointers. 1 ulonglong2 = 16B = 4 floats.
    // batch stride 260 floats = 65 units; k-half = 128 floats = 32 units. (R9 bug: was 8)
    const ulonglong2* wrow  = (const ulonglong2*)(w_s + row * 260 + khalf * 128);
    const ulonglong2* hbase = (const ulonglong2*)h_s + khalf * 32 + b0 * 65;

    for (int step = 0; step < 256; step++) {
        int slot = step & 1;
        int sidx = dir ? (255 - step) : step;

        // prefetch P gate biases for (row, b0..b0+7) — only lanes < 16 need them
        float Pv[8];
        if (lane < 16) {
            const float* Pp = g_P + (size_t)(sidx * 64 + b0) * NJ + dir * 1024 + growp;
            #pragma unroll
            for (int j = 0; j < 8; j++) Pv[j] = Pp[(size_t)j * NJ];
        }

        // wait for chunk cg of h(step), then copy 1KB into batch-major SMEM.
        {
            unsigned v;
            do {
                asm volatile("ld.acquire.gpu.b32 %0, [%1];" : "=r"(v) : "l"(myflag) : "memory");
            } while ((int)v < step);
            const float4* src  = (const float4*)(g_hbuf + ((slot * 2 + dir) * 64 + cg) * 256);
            float4* dst4 = (float4*)h_s;                 // batch stride = 65 float4
            #pragma unroll
            for (int i = 0; i < 16; i++) {
                int b = cq + 4 * i;
                dst4[b * 65 + cg] = __ldcg(src + b);
            }
        }
        __syncthreads();

        // 8 partial dot products (row, batches b0..b0+7, this k-half), f32x2
        ull A0 = 0, A1 = 0, A2 = 0, A3 = 0, A4 = 0, A5 = 0, A6 = 0, A7 = 0;
        #pragma unroll 8
        for (int c = 0; c < 32; c++) {
            ulonglong2 wv = wrow[c];
            ulonglong2 hv;
            hv = hbase[0 * 65 + c]; fma2(A0, wv.x, hv.x); fma2(A0, wv.y, hv.y);
            hv = hbase[1 * 65 + c]; fma2(A1, wv.x, hv.x); fma2(A1, wv.y, hv.y);
            hv = hbase[2 * 65 + c]; fma2(A2, wv.x, hv.x); fma2(A2, wv.y, hv.y);
            hv = hbase[3 * 65 + c]; fma2(A3, wv.x, hv.x); fma2(A3, wv.y, hv.y);
            hv = hbase[4 * 65 + c]; fma2(A4, wv.x, hv.x); fma2(A4, wv.y, hv.y);
            hv = hbase[5 * 65 + c]; fma2(A5, wv.x, hv.x); fma2(A5, wv.y, hv.y);
            hv = hbase[6 * 65 + c]; fma2(A6, wv.x, hv.x); fma2(A6, wv.y, hv.y);
            hv = hbase[7 * 65 + c]; fma2(A7, wv.x, hv.x); fma2(A7, wv.y, hv.y);
        }
        // horizontal add + combine the two k-halves (lanes l <-> l+16)
        float gg[8];
        {
            float2 t;
            t = unpack2(A0); gg[0] = t.x + t.y;
            t = unpack2(A1); gg[1] = t.x + t.y;
            t = unpack2(A2); gg[2] = t.x + t.y;
            t = unpack2(A3); gg[3] = t.x + t.y;
            t = unpack2(A4); gg[4] = t.x + t.y;
            t = unpack2(A5); gg[5] = t.x + t.y;
            t = unpack2(A6); gg[6] = t.x + t.y;
            t = unpack2(A7); gg[7] = t.x + t.y;
        }
        #pragma unroll
        for (int j = 0; j < 8; j++)
            gg[j] += __shfl_xor_sync(0xffffffffu, gg[j], 16);
        if (lane < 16) {
            #pragma unroll
            for (int j = 0; j < 8; j++)
                gate_s[row * 72 + b0 + j] = gg[j] + Pv[j];
        }
        __syncthreads();

        // cell/hidden update: gate order i,f,g,o (gate row = gate*4 + kk2)
        {
            float gi = gate_s[(0  + kk2) * 72 + bb];
            float gf = gate_s[(4  + kk2) * 72 + bb];
            float gG = gate_s[(8  + kk2) * 72 + bb];
            float go = gate_s[(12 + kk2) * 72 + bb];
            float si = 1.f / (1.f + expf(-gi));
            float sf = 1.f / (1.f + expf(-gf));
            float so = 1.f / (1.f + expf(-go));
            float c = sf * c_s[tid] + si * tanhf(gG);
            c_s[tid] = c;
            float h = so * tanhf(c);
            // publish h(step+1) into slot (step+1)&1, chunk gown (contiguous 1KB)
            __stcg(&g_hbuf[(((slot ^ 1) * 2 + dir) * 64 + gown) * 256 + bb * 4 + kk2], h);
            g_Hout[(size_t)dir * ((size_t)NROWS * HID2) + (size_t)(sidx * 64 + bb) * 256 + k0 + kk2] = h;
        }

        // publish flag = step+1 (release; syncthreads orders all threads' stores)
        __syncthreads();
        __threadfence();
        if (tid == 0) {
            unsigned nv = (unsigned)(step + 1);
            asm volatile("st.release.gpu.b32 [%0], %1;" :: "l"(ownflag), "r"(nv) : "memory");
        }
    }
}

// ---------------- kernel 3: output features F[r][t] ----------------
__global__ void __launch_bounds__(256) feats_kernel(
    const float* __restrict__ Wout, const float* __restrict__ bout) {
    int warp = threadIdx.x >> 5;
    int lane = threadIdx.x & 31;
    int r = blockIdx.x * 8 + warp;
    const float* hf = g_Hout + (size_t)r * 256;
    const float* hb = g_Hout + (size_t)NROWS * HID2 + (size_t)r * 256;
    float a[8], c[8];
    #pragma unroll
    for (int q = 0; q < 8; q++) { a[q] = hf[lane * 8 + q]; c[q] = hb[lane * 8 + q]; }
    #pragma unroll
    for (int t = 0; t < NTAG; t++) {
        const float* w = Wout + t * 512 + lane * 8;
        float s = 0.f;
        #pragma unroll
        for (int q = 0; q < 8; q++) s += a[q] * w[q] + c[q] * w[256 + q];
        #pragma unroll
        for (int off = 16; off; off >>= 1) s += __shfl_xor_sync(0xffffffffu, s, off);
        if (lane == 0) g_F[r * NTAG + t] = s + bout[t];
    }
}

// ---------------- kernel 4: Viterbi decode (one warp per batch) ----------------
__global__ void viterbi_kernel(const float* __restrict__ trans, float* __restrict__ out) {
    int b = blockIdx.x;
    int lane = threadIdx.x;
    __shared__ unsigned char bps[256][16];

    float tr[NTAG];
    if (lane < NTAG) {
        #pragma unroll
        for (int p = 0; p < NTAG; p++) tr[p] = trans[lane * NTAG + p];
    } else {
        #pragma unroll
        for (int p = 0; p < NTAG; p++) tr[p] = -10000.0f;
    }
    float fv = (lane == 8) ? 0.f : -10000.0f;   // START_IDX = 8
    const float* fb = g_F + b * (SEQ * NTAG);

    for (int s = 0; s < SEQ; s++) {
        float m = -3.4e38f; int arg = 0;
        #pragma unroll
        for (int p = 0; p < NTAG; p++) {
            float v = __shfl_sync(0xffffffffu, fv, p) + tr[p];
            if (v > m) { m = v; arg = p; }      // strict >: first-max wins (jnp.argmax)
        }
        float feat = 0.f;
        if (lane < NTAG) feat = fb[s * NTAG + lane];
        fv = m + feat;
        if (lane < NTAG) bps[s][lane] = (unsigned char)arg;
    }

    float term = fv;
    if (lane < NTAG) term += trans[9 * NTAG + lane];   // STOP_IDX row = 9
    float best = -3.4e38f; int bt = 0;
    #pragma unroll
    for (int t = 0; t < NTAG; t++) {
        float v = __shfl_sync(0xffffffffu, term, t);
        if (v > best) { best = v; bt = t; }
    }
    __syncwarp();
    if (lane == 0) {
        out[b] = best;                                   // path_score (B,1)
        int cur = bt;
        out[64 + b * SEQ + (SEQ - 1)] = (float)cur;      // path (B,S)
        for (int s = SEQ - 2; s >= 0; s--) {
            cur = bps[s + 1][cur];
            out[64 + b * SEQ + s] = (float)cur;
        }
    }
}

// ---------------- launch ----------------
extern "C" void kernel_launch(void* const* d_in, const int* in_sizes, int n_in,
                              void* d_out, int out_size) {
    const int*   sent  = (const int*)d_in[0];
    const float* emb   = (const float*)d_in[1];
    const float* wih_f = (const float*)d_in[2];
    const float* whh_f = (const float*)d_in[3];
    const float* bih_f = (const float*)d_in[4];
    const float* bhh_f = (const float*)d_in[5];
    const float* wih_b = (const float*)d_in[6];
    const float* whh_b = (const float*)d_in[7];
    const float* bih_b = (const float*)d_in[8];
    const float* bhh_b = (const float*)d_in[9];
    const float* Wout  = (const float*)d_in[10];
    const float* bout  = (const float*)d_in[11];

    // Dict order has transitions last; signature order has it at index 12.
    const float *trans, *h0, *c0;
    if (n_in > 14 && in_sizes[12] == 100) {
        trans = (const float*)d_in[12]; h0 = (const float*)d_in[13]; c0 = (const float*)d_in[14];
    } else {
        h0 = (const float*)d_in[12]; c0 = (const float*)d_in[13]; trans = (const float*)d_in[14];
    }
    float* out = (float*)d_out;

    transpose_wih<<<(EMB * NJ + 255) / 256, 256>>>(wih_f, wih_b);
    init_state<<<128, 256>>>(h0);
    gemm_input<<<8192, 256>>>(sent, emb, bih_f, bhh_f, bih_b, bhh_b);

    const int smem_rec = 22208 * (int)sizeof(float); // 88832 B
    cudaFuncSetAttribute(lstm_recurrent, cudaFuncAttributeMaxDynamicSharedMemorySize, smem_rec);
    lstm_recurrent<<<NCTA_REC, 256, smem_rec>>>(whh_f, whh_b, c0);

    feats_kernel<<<NROWS / 8, 256>>>(Wout, bout);
    viterbi_kernel<<<BAT, 32>>>(trans, out);
}